// round 2
// baseline (speedup 1.0000x reference)
#include <cuda_runtime.h>
#include <math.h>

#define N_VEC   16384
#define K_CODES 8192
#define DDIM    64
#define BN      128
#define BJ      128
#define KC      32                     // k-chunk for codebook tile
#define NTILES  (K_CODES / BJ)         // 64
#define OUT_ELEMS 1048576              // 16*64*32*32

// scratch (no cudaMalloc allowed)
__device__ float g_cnT[DDIM * K_CODES];  // normalized codebook, transposed: [k][j]
__device__ int   g_idx[N_VEC];
__device__ int   g_bin[K_CODES];
__device__ float g_loss;

// ---------------------------------------------------------------------------
__global__ void zero_kernel() {
    int t = blockIdx.x * blockDim.x + threadIdx.x;
    if (t < K_CODES) g_bin[t] = 0;
    if (t == 0) g_loss = 0.0f;
}

// ---------------------------------------------------------------------------
// Normalize codebook rows and write transposed: g_cnT[k*K + j] = embed[j][k]/||embed[j]||
__global__ void normalize_kernel(const float* __restrict__ embed) {
    __shared__ float tile[32][65];
    __shared__ float inv[32];
    int j0 = blockIdx.x * 32;
    int t = threadIdx.x;  // 256 threads

    for (int i = t; i < 32 * 64; i += 256) {
        int r = i >> 6, c = i & 63;
        tile[r][c] = embed[(j0 + r) * 64 + c];
    }
    __syncthreads();
    if (t < 32) {
        float s = 0.0f;
#pragma unroll
        for (int c = 0; c < 64; c++) { float v = tile[t][c]; s += v * v; }
        float nrm = fmaxf(sqrtf(s), 1e-12f);
        inv[t] = 1.0f / nrm;
    }
    __syncthreads();
    for (int i = t; i < 32 * 64; i += 256) {
        int r = i & 31, c = i >> 5;   // consecutive t -> consecutive j (coalesced)
        g_cnT[c * K_CODES + j0 + r] = tile[r][c] * inv[r];
    }
}

// ---------------------------------------------------------------------------
// GEMM-with-running-argmax: block = 128 n-vectors x all 8192 codes.
// Static smem: zs 32KB + cs 16KB = 48KB (no cudaFuncSetAttribute needed).
__global__ void __launch_bounds__(256) argmax_kernel(const float* __restrict__ z) {
    __shared__ float zs[DDIM * BN];   // [64][128]
    __shared__ float cs[KC * BJ];     // [32][128]

    int nbase = blockIdx.x * BN;
    int b = nbase >> 10;
    int hw0 = nbase & 1023;
    const float* zsrc = z + b * 65536 + hw0;   // zsrc[k*1024 + n]
    int t = threadIdx.x;
    int tx = t & 15, ty = t >> 4;

    // load z tile (once): zs[k][n], contiguous in n for each k
#pragma unroll
    for (int i = 0; i < 8; i++) {
        int f4 = t + i * 256;
        int k = f4 >> 5;
        int n4 = (f4 & 31) << 2;
        *(float4*)&zs[k * BN + n4] = *(const float4*)&zsrc[k * 1024 + n4];
    }

    float bv[8];
    int bi[8];
#pragma unroll
    for (int i = 0; i < 8; i++) { bv[i] = -1e30f; bi[i] = 0; }

    for (int tile = 0; tile < NTILES; tile++) {
        int j0 = tile * BJ;

        float acc[8][8];
#pragma unroll
        for (int i = 0; i < 8; i++)
#pragma unroll
            for (int j = 0; j < 8; j++) acc[i][j] = 0.0f;

#pragma unroll
        for (int kc = 0; kc < 2; kc++) {
            __syncthreads();  // protect cs from previous readers
            // load codebook chunk: cs[kk][j] for kk in [0,32)
#pragma unroll
            for (int i = 0; i < 4; i++) {
                int f4 = t + i * 256;        // 1024 float4s = 32*128 floats
                int kk = f4 >> 5;
                int j4 = (f4 & 31) << 2;
                *(float4*)&cs[kk * BJ + j4] =
                    *(const float4*)&g_cnT[(kc * KC + kk) * K_CODES + j0 + j4];
            }
            __syncthreads();

#pragma unroll 8
            for (int kk = 0; kk < KC; kk++) {
                int k = kc * KC + kk;
                float4 A0 = *(float4*)&zs[k * BN + ty * 8];
                float4 A1 = *(float4*)&zs[k * BN + ty * 8 + 4];
                float4 B0 = *(float4*)&cs[kk * BJ + tx * 8];
                float4 B1 = *(float4*)&cs[kk * BJ + tx * 8 + 4];
                float a[8] = {A0.x, A0.y, A0.z, A0.w, A1.x, A1.y, A1.z, A1.w};
                float bb[8] = {B0.x, B0.y, B0.z, B0.w, B1.x, B1.y, B1.z, B1.w};
#pragma unroll
                for (int i = 0; i < 8; i++)
#pragma unroll
                    for (int j = 0; j < 8; j++)
                        acc[i][j] = fmaf(a[i], bb[j], acc[i][j]);
            }
        }

        // running argmax (j ascending -> strict > keeps first-max semantics)
#pragma unroll
        for (int i = 0; i < 8; i++) {
#pragma unroll
            for (int j = 0; j < 8; j++) {
                float v = acc[i][j];
                int idx = j0 + tx * 8 + j;
                if (v > bv[i]) { bv[i] = v; bi[i] = idx; }
            }
        }
    }

    // reduce across the 16 tx lanes (contiguous half-warps share the same rows)
#pragma unroll
    for (int i = 0; i < 8; i++) {
#pragma unroll
        for (int off = 8; off >= 1; off >>= 1) {
            float ov = __shfl_down_sync(0xFFFFFFFFu, bv[i], off);
            int   oi = __shfl_down_sync(0xFFFFFFFFu, bi[i], off);
            if (ov > bv[i] || (ov == bv[i] && oi < bi[i])) { bv[i] = ov; bi[i] = oi; }
        }
    }
    if (tx == 0) {
#pragma unroll
        for (int i = 0; i < 8; i++) {
            int n = nbase + ty * 8 + i;
            g_idx[n] = bi[i];
            atomicAdd(&g_bin[bi[i]], 1);
        }
    }
}

// ---------------------------------------------------------------------------
// Gather z_q into out (b,c,h,w layout) + accumulate loss partials
__global__ void gather_kernel(const float* __restrict__ z,
                              const float* __restrict__ embed,
                              float* __restrict__ out) {
    int e4 = blockIdx.x * blockDim.x + threadIdx.x;  // 262144 float4s
    int e = e4 * 4;
    int b = e >> 16;
    int c = (e >> 10) & 63;
    int hw = e & 1023;
    int n = (b << 10) + hw;

    float4 zv = *(const float4*)&z[e];
    float4 q;
    q.x = embed[g_idx[n + 0] * 64 + c];
    q.y = embed[g_idx[n + 1] * 64 + c];
    q.z = embed[g_idx[n + 2] * 64 + c];
    q.w = embed[g_idx[n + 3] * 64 + c];
    *(float4*)&out[e] = q;

    float d0 = q.x - zv.x, d1 = q.y - zv.y, d2 = q.z - zv.z, d3 = q.w - zv.w;
    float s = d0 * d0 + d1 * d1 + d2 * d2 + d3 * d3;

    // block reduce
#pragma unroll
    for (int off = 16; off >= 1; off >>= 1)
        s += __shfl_xor_sync(0xFFFFFFFFu, s, off);
    __shared__ float red[8];
    int lane = threadIdx.x & 31, wid = threadIdx.x >> 5;
    if (lane == 0) red[wid] = s;
    __syncthreads();
    if (wid == 0) {
        s = (lane < 8) ? red[lane] : 0.0f;
#pragma unroll
        for (int off = 4; off >= 1; off >>= 1)
            s += __shfl_xor_sync(0xFFFFFFFFu, s, off);
        if (lane == 0) atomicAdd(&g_loss, s);
    }
}

// ---------------------------------------------------------------------------
// Write loss scalar, indices-as-float, bin_count-as-float
__global__ void finalize_kernel(float* __restrict__ out) {
    int t = blockIdx.x * blockDim.x + threadIdx.x;  // 24576 threads
    if (t == 0)
        out[OUT_ELEMS] = 1.25f * g_loss * (1.0f / (float)OUT_ELEMS);
    if (t < N_VEC)
        out[OUT_ELEMS + 1 + t] = (float)g_idx[t];
    if (t < K_CODES)
        out[OUT_ELEMS + 1 + N_VEC + t] = (float)g_bin[t];
}

// ---------------------------------------------------------------------------
extern "C" void kernel_launch(void* const* d_in, const int* in_sizes, int n_in,
                              void* d_out, int out_size) {
    const float* z     = (const float*)d_in[0];       // [16,64,32,32]
    const float* embed = (const float*)d_in[1];       // [8192,64]
    float* out = (float*)d_out;

    zero_kernel<<<32, 256>>>();
    normalize_kernel<<<K_CODES / 32, 256>>>(embed);
    argmax_kernel<<<N_VEC / BN, 256>>>(z);
    gather_kernel<<<OUT_ELEMS / 4 / 256, 256>>>(z, embed, out);
    finalize_kernel<<<96, 256>>>(out);
}